// round 9
// baseline (speedup 1.0000x reference)
#include <cuda_runtime.h>

#define NN 50000
#define EE 800000
#define DD 96
#define NV4 (NN * DD / 4)

// ---------------- scratch (device globals; no allocation allowed) ----------
__device__ __align__(256) float g_deg[NN];
__device__ __align__(256) float g_dis[NN];
__device__ __align__(256) float g_norm[EE];
__device__ __align__(256) float g_T1[NN * DD];
__device__ __align__(256) float g_P[NN * DD];
__device__ __align__(256) float g_pA[NN * DD];   // x@W0 + bias
__device__ __align__(256) float g_pB[NN * DD];   // T1@W1
__device__ __align__(256) float g_pC[NN * DD];   // (2P-x)@W2
__device__ __align__(256) float g_acc[NN * DD];  // combined pre-BN output
__device__ __align__(256) float g_colsum[DD];
__device__ __align__(256) float g_colsumsq[DD];
__device__ __align__(256) float g_scale[DD];
__device__ __align__(256) float g_shift[DD];

// ---- host-side stream/events, created at static init (before checkpoints) --
static cudaStream_t g_s2 = [] {
    cudaStream_t t; cudaStreamCreateWithFlags(&t, cudaStreamNonBlocking); return t;
}();
static cudaEvent_t g_eFork = [] {
    cudaEvent_t e; cudaEventCreateWithFlags(&e, cudaEventDisableTiming); return e;
}();
static cudaEvent_t g_e1 = [] {
    cudaEvent_t e; cudaEventCreateWithFlags(&e, cudaEventDisableTiming); return e;
}();
static cudaEvent_t g_e2 = [] {
    cudaEvent_t e; cudaEventCreateWithFlags(&e, cudaEventDisableTiming); return e;
}();
static cudaEvent_t g_eJoin = [] {
    cudaEvent_t e; cudaEventCreateWithFlags(&e, cudaEventDisableTiming); return e;
}();

// ---------------- zero scratch ---------------------------------------------
__global__ void zero_kernel() {
    int tid = blockIdx.x * blockDim.x + threadIdx.x;
    int stride = gridDim.x * blockDim.x;
    float4* t1 = reinterpret_cast<float4*>(g_T1);
    float4* p  = reinterpret_cast<float4*>(g_P);
    float4 z = make_float4(0.f, 0.f, 0.f, 0.f);
    for (int i = tid; i < NV4; i += stride) { t1[i] = z; p[i] = z; }
    for (int i = tid; i < NN; i += stride) g_deg[i] = 0.f;
    if (tid < DD) { g_colsum[tid] = 0.f; g_colsumsq[tid] = 0.f; }
}

// ---------------- degree / normalization (round-2 verbatim) -----------------
__global__ void deg_kernel(const int* __restrict__ ei) {
    int e = blockIdx.x * blockDim.x + threadIdx.x;
    if (e >= EE) return;
    int r = ei[e], c = ei[EE + e];
    if (r != c) atomicAdd(&g_deg[r], 1.0f);
}

__global__ void dis_kernel() {
    int i = blockIdx.x * blockDim.x + threadIdx.x;
    if (i >= NN) return;
    float d = g_deg[i];
    g_dis[i] = (d > 0.f) ? rsqrtf(fmaxf(d, 1e-12f)) : 0.f;
}

__global__ void norm_kernel(const int* __restrict__ ei) {
    int e = blockIdx.x * blockDim.x + threadIdx.x;
    if (e >= EE) return;
    int r = ei[e], c = ei[EE + e];
    g_norm[e] = (r != c) ? (-g_dis[r] * g_dis[c]) : 0.f;
}

// ---------------- SpMM (round-2 verbatim) -----------------------------------
__global__ void spmm_kernel(int pass, const float* __restrict__ x,
                            const int* __restrict__ ei) {
    const float4* src = (pass == 0) ? reinterpret_cast<const float4*>(x)
                                    : reinterpret_cast<const float4*>(g_T1);
    float* dst = (pass == 0) ? g_T1 : g_P;

    int warp_id = (blockIdx.x * blockDim.x + threadIdx.x) >> 5;
    int lane = threadIdx.x & 31;
    int e = warp_id * 4 + (lane >> 3);
    if (e >= EE) return;

    float nrm = g_norm[e];
    if (nrm == 0.f) return;
    int r = ei[e], c = ei[EE + e];
    int chunk = lane & 7;

    const float4* srow = src + r * (DD / 4);
    float* drow = dst + c * DD;

#pragma unroll
    for (int s = 0; s < 3; s++) {
        int idx = chunk + 8 * s;
        float4 v = __ldg(srow + idx);
        float a = nrm * v.x, b = nrm * v.y, cc = nrm * v.z, d = nrm * v.w;
        float* addr = drow + idx * 4;
        asm volatile("red.global.add.v4.f32 [%0], {%1, %2, %3, %4};"
                     :: "l"(addr), "f"(a), "f"(b), "f"(cc), "f"(d)
                     : "memory");
    }
}

// ---------------- matrix-split GEMM (round-7 verbatim logic) ----------------
#define GT 192
#define RPB 64
#define WS_STRIDE 100
#define GBLK ((NN + RPB - 1) / RPB)                    // 782
#define SMEM_FLOATS (DD * WS_STRIDE + DD + RPB * DD)
#define SMEM_BYTES (SMEM_FLOATS * 4)                   // 63360 B -> 3 CTAs/SM

__global__ __launch_bounds__(GT, 3)
void gemm_kernel(int m, const float* __restrict__ x, const float* __restrict__ W,
                 const float* __restrict__ bias) {
    extern __shared__ float smem[];
    float* Ws = smem;                    // [96*100] transposed
    float* bs = Ws + DD * WS_STRIDE;     // [96]
    float* xs = bs + DD;                 // [64*96]

    int tid = threadIdx.x;
    const float* Wm = W + m * DD * DD;

    for (int i = tid; i < DD * DD; i += GT) {
        int k = i / DD, j = i - k * DD;
        Ws[j * WS_STRIDE + k] = Wm[i];
    }
    if (m == 0 && tid < DD) bs[tid] = bias[tid];

    int base = blockIdx.x * RPB;

    {
        float4* xs4 = reinterpret_cast<float4*>(xs);
        const float4* x4 = reinterpret_cast<const float4*>(x);
        const float4* t14 = reinterpret_cast<const float4*>(g_T1);
        const float4* p4 = reinterpret_cast<const float4*>(g_P);
        for (int i = tid; i < RPB * (DD / 4); i += GT) {
            int r = i / (DD / 4);
            int row = base + r;
            float4 v = make_float4(0.f, 0.f, 0.f, 0.f);
            if (row < NN) {
                int gi = row * (DD / 4) + (i - r * (DD / 4));
                if (m == 0) v = __ldg(x4 + gi);
                else if (m == 1) v = t14[gi];
                else {
                    float4 pv = p4[gi];
                    float4 xv = __ldg(x4 + gi);
                    v = make_float4(2.f * pv.x - xv.x, 2.f * pv.y - xv.y,
                                    2.f * pv.z - xv.z, 2.f * pv.w - xv.w);
                }
            }
            xs4[i] = v;
        }
    }
    __syncthreads();

    int tx = tid % 24;
    int ty = tid / 24;

    float acc[8][4];
#pragma unroll
    for (int r = 0; r < 8; r++)
#pragma unroll
        for (int jj = 0; jj < 4; jj++) acc[r][jj] = 0.f;

    const float* xrow = xs + ty * 8 * DD;

    for (int k = 0; k < DD; k += 4) {
        float4 w[4];
#pragma unroll
        for (int jj = 0; jj < 4; jj++)
            w[jj] = *reinterpret_cast<const float4*>(
                        &Ws[(tx + jj * 24) * WS_STRIDE + k]);
#pragma unroll
        for (int r = 0; r < 8; r++) {
            float4 xv = *reinterpret_cast<const float4*>(&xrow[r * DD + k]);
#pragma unroll
            for (int jj = 0; jj < 4; jj++) {
                float s = acc[r][jj];
                s += xv.x * w[jj].x; s += xv.y * w[jj].y;
                s += xv.z * w[jj].z; s += xv.w * w[jj].w;
                acc[r][jj] = s;
            }
        }
    }

    float* part = (m == 0) ? g_pA : (m == 1) ? g_pB : g_pC;

#pragma unroll
    for (int jj = 0; jj < 4; jj++) {
        int j = tx + jj * 24;
        float bj = (m == 0) ? bs[j] : 0.f;
#pragma unroll
        for (int r = 0; r < 8; r++) {
            int row = base + ty * 8 + r;
            if (row < NN)
                part[row * DD + j] = acc[r][jj] + bj;
        }
    }
}

// ---------------- combine partials + column stats (round-7 verbatim) --------
#define CROWS 256
__global__ __launch_bounds__(GT, 8)
void combine_kernel() {
    int tid = threadIdx.x;
    int j = tid % DD;
    int rh = tid / DD;
    int base = blockIdx.x * CROWS;
    float s = 0.f, s2 = 0.f;
    for (int r = rh; r < CROWS; r += 2) {
        int row = base + r;
        if (row >= NN) break;
        int i = row * DD + j;
        float v = g_pA[i] + g_pB[i] + g_pC[i];
        g_acc[i] = v;
        s += v; s2 += v * v;
    }
    atomicAdd(&g_colsum[j], s);
    atomicAdd(&g_colsumsq[j], s2);
}

// ---------------- BatchNorm finalize ---------------------------------------
__global__ void bn_stats_kernel(const float* __restrict__ gamma,
                                const float* __restrict__ beta) {
    int j = threadIdx.x;
    if (j >= DD) return;
    float inv_n = 1.0f / (float)NN;
    float mean = g_colsum[j] * inv_n;
    float var = g_colsumsq[j] * inv_n - mean * mean;
    var = fmaxf(var, 0.f);
    float istd = rsqrtf(var + 1e-5f);
    float sc = gamma[j] * istd;
    g_scale[j] = sc;
    g_shift[j] = beta[j] - mean * sc;
}

__global__ void bn_apply_kernel(float* __restrict__ out) {
    __shared__ float sc[DD], sh[DD];
    if (threadIdx.x < DD) {
        sc[threadIdx.x] = g_scale[threadIdx.x];
        sh[threadIdx.x] = g_shift[threadIdx.x];
    }
    __syncthreads();
    int tid = blockIdx.x * blockDim.x + threadIdx.x;
    int stride = gridDim.x * blockDim.x;
    const float4* in4 = reinterpret_cast<const float4*>(g_acc);
    float4* o4 = reinterpret_cast<float4*>(out);
    for (int i = tid; i < NV4; i += stride) {
        int c4 = i % (DD / 4);
        int j = c4 * 4;
        float4 v = in4[i];
        o4[i] = make_float4(v.x * sc[j]     + sh[j],
                            v.y * sc[j + 1] + sh[j + 1],
                            v.z * sc[j + 2] + sh[j + 2],
                            v.w * sc[j + 3] + sh[j + 3]);
    }
}

// ---------------- launch: fork/join graph with concurrent GEMM branch -------
extern "C" void kernel_launch(void* const* d_in, const int* in_sizes, int n_in,
                              void* d_out, int out_size) {
    const float* x     = (const float*)d_in[0];
    const int*   ei    = (const int*)d_in[1];
    const float* W     = (const float*)d_in[2];
    const float* bias  = (const float*)d_in[3];
    const float* gamma = (const float*)d_in[4];
    const float* beta  = (const float*)d_in[5];
    float* out = (float*)d_out;

    cudaFuncSetAttribute(gemm_kernel,
                         cudaFuncAttributeMaxDynamicSharedMemorySize, SMEM_BYTES);

    // fork side stream off the (possibly capturing) main stream
    cudaEventRecord(g_eFork, 0);
    cudaStreamWaitEvent(g_s2, g_eFork, 0);

    // side stream: gemmA depends only on x
    gemm_kernel<<<GBLK, GT, SMEM_BYTES, g_s2>>>(0, x, W, bias);

    // main stream: preprocessing + spmm1
    zero_kernel<<<2048, 256>>>();
    deg_kernel<<<(EE + 255) / 256, 256>>>(ei);
    dis_kernel<<<(NN + 255) / 256, 256>>>();
    norm_kernel<<<(EE + 255) / 256, 256>>>(ei);
    spmm_kernel<<<EE / 32, 256>>>(0, x, ei);          // T1 = L_hat @ x
    cudaEventRecord(g_e1, 0);

    // side stream: gemmB after spmm1 (reads g_T1)
    cudaStreamWaitEvent(g_s2, g_e1, 0);
    gemm_kernel<<<GBLK, GT, SMEM_BYTES, g_s2>>>(1, x, W, bias);

    // main stream: spmm2 concurrent with gemmB
    spmm_kernel<<<EE / 32, 256>>>(1, x, ei);          // P = L_hat @ T1
    cudaEventRecord(g_e2, 0);

    // side stream: gemmC after spmm2 (reads g_P)
    cudaStreamWaitEvent(g_s2, g_e2, 0);
    gemm_kernel<<<GBLK, GT, SMEM_BYTES, g_s2>>>(2, x, W, bias);
    cudaEventRecord(g_eJoin, g_s2);

    // main stream: join, then combine + BN
    cudaStreamWaitEvent(0, g_eJoin, 0);
    combine_kernel<<<(NN + CROWS - 1) / CROWS, GT>>>();
    bn_stats_kernel<<<1, 128>>>(gamma, beta);
    bn_apply_kernel<<<2048, 256>>>(out);
}

// round 10
// speedup vs baseline: 1.1930x; 1.1930x over previous
#include <cuda_runtime.h>

#define NN 50000
#define EE 800000
#define DD 96
#define NV4 (NN * DD / 4)   // float4 count of an [N,96] array

// ---------------- scratch (device globals; no allocation allowed) ----------
__device__ __align__(256) float g_deg[NN];
__device__ __align__(256) float g_norm[EE];
__device__ __align__(256) float g_T1[NN * DD];
__device__ __align__(256) float g_P[NN * DD];
__device__ __align__(256) float g_acc[NN * DD];   // pre-BN output
__device__ __align__(256) float g_colsum[DD];
__device__ __align__(256) float g_colsumsq[DD];

// ---------------- zero scratch ---------------------------------------------
__global__ void zero_kernel() {
    int tid = blockIdx.x * blockDim.x + threadIdx.x;
    int stride = gridDim.x * blockDim.x;
    float4* t1 = reinterpret_cast<float4*>(g_T1);
    float4* p  = reinterpret_cast<float4*>(g_P);
    float4 z = make_float4(0.f, 0.f, 0.f, 0.f);
    for (int i = tid; i < NV4; i += stride) { t1[i] = z; p[i] = z; }
    for (int i = tid; i < NN; i += stride) g_deg[i] = 0.f;
    if (tid < DD) { g_colsum[tid] = 0.f; g_colsumsq[tid] = 0.f; }
}

// ---------------- degree histogram -----------------------------------------
__global__ void deg_kernel(const int* __restrict__ ei) {
    int e = blockIdx.x * blockDim.x + threadIdx.x;
    if (e >= EE) return;
    int r = ei[e], c = ei[EE + e];
    if (r != c) atomicAdd(&g_deg[r], 1.0f);
}

// ---------------- edge norm (dis folded in: rsqrt computed inline) ----------
__global__ void norm_kernel(const int* __restrict__ ei) {
    int e = blockIdx.x * blockDim.x + threadIdx.x;
    if (e >= EE) return;
    int r = ei[e], c = ei[EE + e];
    float nrm = 0.f;
    if (r != c) {
        float dr = g_deg[r], dc = g_deg[c];
        float ir = (dr > 0.f) ? rsqrtf(fmaxf(dr, 1e-12f)) : 0.f;
        float ic = (dc > 0.f) ? rsqrtf(fmaxf(dc, 1e-12f)) : 0.f;
        nrm = -ir * ic;
    }
    g_norm[e] = nrm;
}

// ---------------- SpMM (round-2 verbatim): dst[col] += norm * src[row] -----
__global__ void spmm_kernel(int pass, const float* __restrict__ x,
                            const int* __restrict__ ei) {
    const float4* src = (pass == 0) ? reinterpret_cast<const float4*>(x)
                                    : reinterpret_cast<const float4*>(g_T1);
    float* dst = (pass == 0) ? g_T1 : g_P;

    int warp_id = (blockIdx.x * blockDim.x + threadIdx.x) >> 5;
    int lane = threadIdx.x & 31;
    int e = warp_id * 4 + (lane >> 3);
    if (e >= EE) return;

    float nrm = g_norm[e];
    if (nrm == 0.f) return;
    int r = ei[e], c = ei[EE + e];
    int chunk = lane & 7;

    const float4* srow = src + r * (DD / 4);
    float* drow = dst + c * DD;

#pragma unroll
    for (int s = 0; s < 3; s++) {
        int idx = chunk + 8 * s;          // 0..23
        float4 v = __ldg(srow + idx);
        float a = nrm * v.x, b = nrm * v.y, cc = nrm * v.z, d = nrm * v.w;
        float* addr = drow + idx * 4;     // 16B aligned
        asm volatile("red.global.add.v4.f32 [%0], {%1, %2, %3, %4};"
                     :: "l"(addr), "f"(a), "f"(b), "f"(cc), "f"(d)
                     : "memory");
    }
}

// ---------------- fused GEMM + bias + column-stat accumulation -------------
// out = x@W0 + T1@W1 + (2P - x)@W2 + bias ; colsum/colsumsq for BN.
// 384 threads (12 warps, 3/SMSP), 4 rows/thread — latency cover for the
// 1-CTA/SM smem-heavy config. Same smem layout/tiles as round 2.
#define GEMM_THREADS 384
#define RPB 64              // rows per block
#define WS_STRIDE 100
#define WS_MAT (DD * WS_STRIDE)                 // 9600 floats per matrix
#define SMEM_FLOATS (3 * WS_MAT + DD + 3 * RPB * DD)
#define SMEM_BYTES (SMEM_FLOATS * 4)

__global__ __launch_bounds__(GEMM_THREADS, 1)
void gemm_kernel(const float* __restrict__ x, const float* __restrict__ W,
                 const float* __restrict__ bias) {
    extern __shared__ float smem[];
    float* Ws  = smem;                   // [3][96*100]
    float* bs  = Ws + 3 * WS_MAT;        // [96]
    float* xs  = bs + DD;                // [64*96]
    float* t1s = xs + RPB * DD;          // [64*96]
    float* t2s = t1s + RPB * DD;         // [64*96]

    int tid = threadIdx.x;

    // stage W transposed: Ws[kk][j*100 + k] = W[kk][k][j]
    for (int i = tid; i < 3 * DD * DD; i += GEMM_THREADS) {
        int kk = i / (DD * DD);
        int rem = i - kk * DD * DD;
        int k = rem / DD;
        int j = rem - k * DD;
        Ws[kk * WS_MAT + j * WS_STRIDE + k] = W[i];
    }
    if (tid < DD) bs[tid] = bias[tid];

    int base = blockIdx.x * RPB;

    // stage 64 rows of x, T1 and T2 = 2P - x (float4)
    {
        const float4* x4  = reinterpret_cast<const float4*>(x);
        const float4* t14 = reinterpret_cast<const float4*>(g_T1);
        const float4* p4  = reinterpret_cast<const float4*>(g_P);
        float4* xs4  = reinterpret_cast<float4*>(xs);
        float4* t1s4 = reinterpret_cast<float4*>(t1s);
        float4* t2s4 = reinterpret_cast<float4*>(t2s);
        for (int i = tid; i < RPB * (DD / 4); i += GEMM_THREADS) {
            int r = i / (DD / 4);
            int row = base + r;
            float4 xv = make_float4(0.f, 0.f, 0.f, 0.f);
            float4 t1v = xv, t2v = xv;
            if (row < NN) {
                int gi = row * (DD / 4) + (i - r * (DD / 4));
                xv = __ldg(x4 + gi);
                t1v = t14[gi];
                float4 pv = p4[gi];
                t2v = make_float4(2.f * pv.x - xv.x, 2.f * pv.y - xv.y,
                                  2.f * pv.z - xv.z, 2.f * pv.w - xv.w);
            }
            xs4[i] = xv; t1s4[i] = t1v; t2s4[i] = t2v;
        }
    }
    __syncthreads();

    int tx = tid % 24;           // j in {tx, tx+24, tx+48, tx+72}
    int ty = tid / 24;           // 0..15 -> rows [base + ty*4, base + ty*4 + 4)

    float acc[4][4];
#pragma unroll
    for (int r = 0; r < 4; r++)
#pragma unroll
        for (int jj = 0; jj < 4; jj++)
            acc[r][jj] = bs[tx + jj * 24];

    const float* xrow  = xs  + ty * 4 * DD;
    const float* t1row = t1s + ty * 4 * DD;
    const float* t2row = t2s + ty * 4 * DD;

    for (int k = 0; k < DD; k += 4) {
        float4 w0[4], w1[4], w2[4];
#pragma unroll
        for (int jj = 0; jj < 4; jj++) {
            int j = tx + jj * 24;
            w0[jj] = *reinterpret_cast<const float4*>(&Ws[0 * WS_MAT + j * WS_STRIDE + k]);
            w1[jj] = *reinterpret_cast<const float4*>(&Ws[1 * WS_MAT + j * WS_STRIDE + k]);
            w2[jj] = *reinterpret_cast<const float4*>(&Ws[2 * WS_MAT + j * WS_STRIDE + k]);
        }
#pragma unroll
        for (int r = 0; r < 4; r++) {
            float4 xv = *reinterpret_cast<const float4*>(&xrow[r * DD + k]);
            float4 av = *reinterpret_cast<const float4*>(&t1row[r * DD + k]);
            float4 bv = *reinterpret_cast<const float4*>(&t2row[r * DD + k]);
#pragma unroll
            for (int jj = 0; jj < 4; jj++) {
                float s = acc[r][jj];
                s += xv.x * w0[jj].x; s += xv.y * w0[jj].y;
                s += xv.z * w0[jj].z; s += xv.w * w0[jj].w;
                s += av.x * w1[jj].x; s += av.y * w1[jj].y;
                s += av.z * w1[jj].z; s += av.w * w1[jj].w;
                s += bv.x * w2[jj].x; s += bv.y * w2[jj].y;
                s += bv.z * w2[jj].z; s += bv.w * w2[jj].w;
                acc[r][jj] = s;
            }
        }
    }

    // epilogue: write pre-BN output + accumulate column stats
#pragma unroll
    for (int jj = 0; jj < 4; jj++) {
        int j = tx + jj * 24;
        float s = 0.f, s2 = 0.f;
#pragma unroll
        for (int r = 0; r < 4; r++) {
            int row = base + ty * 4 + r;
            if (row < NN) {
                float v = acc[r][jj];
                g_acc[row * DD + j] = v;
                s += v; s2 += v * v;
            }
        }
        atomicAdd(&g_colsum[j], s);
        atomicAdd(&g_colsumsq[j], s2);
    }
}

// ---------------- BatchNorm: stats finalize fused into apply ----------------
__global__ void bn_apply_kernel(const float* __restrict__ gamma,
                                const float* __restrict__ beta,
                                float* __restrict__ out) {
    __shared__ float sc[DD], sh[DD];
    if (threadIdx.x < DD) {
        int j = threadIdx.x;
        float inv_n = 1.0f / (float)NN;
        float mean = g_colsum[j] * inv_n;
        float var = fmaxf(g_colsumsq[j] * inv_n - mean * mean, 0.f);
        float istd = rsqrtf(var + 1e-5f);
        float s = gamma[j] * istd;
        sc[j] = s;
        sh[j] = beta[j] - mean * s;
    }
    __syncthreads();
    int tid = blockIdx.x * blockDim.x + threadIdx.x;
    int stride = gridDim.x * blockDim.x;
    const float4* in4 = reinterpret_cast<const float4*>(g_acc);
    float4* o4 = reinterpret_cast<float4*>(out);
    for (int i = tid; i < NV4; i += stride) {
        int c4 = i % (DD / 4);
        int j = c4 * 4;
        float4 v = in4[i];
        o4[i] = make_float4(v.x * sc[j]     + sh[j],
                            v.y * sc[j + 1] + sh[j + 1],
                            v.z * sc[j + 2] + sh[j + 2],
                            v.w * sc[j + 3] + sh[j + 3]);
    }
}

// ---------------- launch ----------------------------------------------------
extern "C" void kernel_launch(void* const* d_in, const int* in_sizes, int n_in,
                              void* d_out, int out_size) {
    const float* x     = (const float*)d_in[0];
    const int*   ei    = (const int*)d_in[1];
    const float* W     = (const float*)d_in[2];
    const float* bias  = (const float*)d_in[3];
    const float* gamma = (const float*)d_in[4];
    const float* beta  = (const float*)d_in[5];
    float* out = (float*)d_out;

    cudaFuncSetAttribute(gemm_kernel,
                         cudaFuncAttributeMaxDynamicSharedMemorySize, SMEM_BYTES);

    zero_kernel<<<2048, 256>>>();
    deg_kernel<<<(EE + 255) / 256, 256>>>(ei);
    norm_kernel<<<(EE + 255) / 256, 256>>>(ei);
    // prop 1: T1 = L_hat @ x
    spmm_kernel<<<EE / 32, 256>>>(0, x, ei);
    // prop 2: P = L_hat @ T1  (T2 = 2P - x computed in GEMM)
    spmm_kernel<<<EE / 32, 256>>>(1, x, ei);
    gemm_kernel<<<(NN + RPB - 1) / RPB, GEMM_THREADS, SMEM_BYTES>>>(x, W, bias);
    bn_apply_kernel<<<2048, 256>>>(gamma, beta, out);
}

// round 11
// speedup vs baseline: 1.2200x; 1.0226x over previous
#include <cuda_runtime.h>

#define NN 50000
#define EE 800000
#define DD 96
#define NV4 (NN * DD / 4)   // float4 count of an [N,96] array

// ---------------- scratch (device globals; no allocation allowed) ----------
__device__ __align__(256) float g_deg[NN];
__device__ __align__(256) uint2 g_edge[EE];      // {(r<<16)|c (unsigned), norm bits}
__device__ __align__(256) float g_T1[NN * DD];
__device__ __align__(256) float g_P[NN * DD];
__device__ __align__(256) float g_acc[NN * DD];  // pre-BN output
__device__ __align__(256) float g_colsum[DD];
__device__ __align__(256) float g_colsumsq[DD];

// ---------------- packed f32x2 FMA (SASS FFMA2) -----------------------------
__device__ __forceinline__ void ffma2(unsigned long long& d,
                                      unsigned long long a,
                                      unsigned long long b) {
    asm("fma.rn.f32x2 %0, %1, %2, %0;" : "+l"(d) : "l"(a), "l"(b));
}

// ---------------- zero scratch ---------------------------------------------
__global__ void zero_kernel() {
    int tid = blockIdx.x * blockDim.x + threadIdx.x;
    int stride = gridDim.x * blockDim.x;
    float4* t1 = reinterpret_cast<float4*>(g_T1);
    float4* p  = reinterpret_cast<float4*>(g_P);
    float4 z = make_float4(0.f, 0.f, 0.f, 0.f);
    for (int i = tid; i < NV4; i += stride) { t1[i] = z; p[i] = z; }
    for (int i = tid; i < NN; i += stride) g_deg[i] = 0.f;
    if (tid < DD) { g_colsum[tid] = 0.f; g_colsumsq[tid] = 0.f; }
}

// ---------------- degree histogram -----------------------------------------
__global__ void deg_kernel(const int* __restrict__ ei) {
    int e = blockIdx.x * blockDim.x + threadIdx.x;
    if (e >= EE) return;
    int r = ei[e], c = ei[EE + e];
    if (r != c) atomicAdd(&g_deg[r], 1.0f);
}

// ---------------- packed edge list with norm (dis inline) -------------------
__global__ void edge_build_kernel(const int* __restrict__ ei) {
    int e = blockIdx.x * blockDim.x + threadIdx.x;
    if (e >= EE) return;
    int r = ei[e], c = ei[EE + e];
    float nrm = 0.f;
    if (r != c) {
        float dr = g_deg[r], dc = g_deg[c];
        float ir = (dr > 0.f) ? rsqrtf(fmaxf(dr, 1e-12f)) : 0.f;
        float ic = (dc > 0.f) ? rsqrtf(fmaxf(dc, 1e-12f)) : 0.f;
        nrm = -ir * ic;
    }
    g_edge[e] = make_uint2(((unsigned)r << 16) | (unsigned)c,
                           (unsigned)__float_as_int(nrm));
}

// ---------------- SpMM: dst[col] += norm[e] * src[row] ---------------------
// Warp handles 4 edges; 8 lanes per edge; each lane moves 3 float4.
// One 8B packed-edge load per edge; scatter via red.global.add.v4.f32.
__global__ void spmm_kernel(int pass, const float* __restrict__ x) {
    const float4* src = (pass == 0) ? reinterpret_cast<const float4*>(x)
                                    : reinterpret_cast<const float4*>(g_T1);
    float* dst = (pass == 0) ? g_T1 : g_P;

    int warp_id = (blockIdx.x * blockDim.x + threadIdx.x) >> 5;
    int lane = threadIdx.x & 31;
    int e = warp_id * 4 + (lane >> 3);
    if (e >= EE) return;

    uint2 ed = g_edge[e];
    float nrm = __int_as_float((int)ed.y);
    if (nrm == 0.f) return;
    int r = (int)(ed.x >> 16);        // logical shift (unsigned)
    int c = (int)(ed.x & 0xFFFFu);
    int chunk = lane & 7;

    const float4* srow = src + r * (DD / 4);
    float* drow = dst + c * DD;

#pragma unroll
    for (int s = 0; s < 3; s++) {
        int idx = chunk + 8 * s;          // 0..23
        float4 v = __ldg(srow + idx);
        float a = nrm * v.x, b = nrm * v.y, cc = nrm * v.z, d = nrm * v.w;
        float* addr = drow + idx * 4;     // 16B aligned
        asm volatile("red.global.add.v4.f32 [%0], {%1, %2, %3, %4};"
                     :: "l"(addr), "f"(a), "f"(b), "f"(cc), "f"(d)
                     : "memory");
    }
}

// ---------------- fused GEMM + bias + column-stat accumulation -------------
// out = x@W0 + T1@W1 + (2P - x)@W2 + bias ; colsum/colsumsq for BN.
// 384 threads (12 warps, 3/SMSP), 4 rows/thread, FFMA2 inner loop
// (acc lanes = even-k / odd-k partials, summed in epilogue).
#define GEMM_THREADS 384
#define RPB 64              // rows per block
#define WS_STRIDE 100
#define WS_MAT (DD * WS_STRIDE)                 // 9600 floats per matrix
#define SMEM_FLOATS (3 * WS_MAT + DD + 3 * RPB * DD)
#define SMEM_BYTES (SMEM_FLOATS * 4)

__global__ __launch_bounds__(GEMM_THREADS, 1)
void gemm_kernel(const float* __restrict__ x, const float* __restrict__ W,
                 const float* __restrict__ bias) {
    extern __shared__ float smem[];
    float* Ws  = smem;                   // [3][96*100]
    float* bs  = Ws + 3 * WS_MAT;        // [96]
    float* xs  = bs + DD;                // [64*96]
    float* t1s = xs + RPB * DD;          // [64*96]
    float* t2s = t1s + RPB * DD;         // [64*96]

    int tid = threadIdx.x;

    // stage W transposed: Ws[kk][j*100 + k] = W[kk][k][j]
    for (int i = tid; i < 3 * DD * DD; i += GEMM_THREADS) {
        int kk = i / (DD * DD);
        int rem = i - kk * DD * DD;
        int k = rem / DD;
        int j = rem - k * DD;
        Ws[kk * WS_MAT + j * WS_STRIDE + k] = W[i];
    }
    if (tid < DD) bs[tid] = bias[tid];

    int base = blockIdx.x * RPB;

    // stage 64 rows of x, T1 and T2 = 2P - x (float4)
    {
        const float4* x4  = reinterpret_cast<const float4*>(x);
        const float4* t14 = reinterpret_cast<const float4*>(g_T1);
        const float4* p4  = reinterpret_cast<const float4*>(g_P);
        float4* xs4  = reinterpret_cast<float4*>(xs);
        float4* t1s4 = reinterpret_cast<float4*>(t1s);
        float4* t2s4 = reinterpret_cast<float4*>(t2s);
        for (int i = tid; i < RPB * (DD / 4); i += GEMM_THREADS) {
            int r = i / (DD / 4);
            int row = base + r;
            float4 xv = make_float4(0.f, 0.f, 0.f, 0.f);
            float4 t1v = xv, t2v = xv;
            if (row < NN) {
                int gi = row * (DD / 4) + (i - r * (DD / 4));
                xv = __ldg(x4 + gi);
                t1v = t14[gi];
                float4 pv = p4[gi];
                t2v = make_float4(2.f * pv.x - xv.x, 2.f * pv.y - xv.y,
                                  2.f * pv.z - xv.z, 2.f * pv.w - xv.w);
            }
            xs4[i] = xv; t1s4[i] = t1v; t2s4[i] = t2v;
        }
    }
    __syncthreads();

    int tx = tid % 24;           // j in {tx, tx+24, tx+48, tx+72}
    int ty = tid / 24;           // 0..15 -> rows [base + ty*4, base + ty*4 + 4)

    // packed accumulators: lane0 = even-k partial, lane1 = odd-k partial
    unsigned long long acc[4][4];
#pragma unroll
    for (int r = 0; r < 4; r++)
#pragma unroll
        for (int jj = 0; jj < 4; jj++)
            acc[r][jj] = 0ULL;

    const float* xrow  = xs  + ty * 4 * DD;
    const float* t1row = t1s + ty * 4 * DD;
    const float* t2row = t2s + ty * 4 * DD;

    for (int k = 0; k < DD; k += 4) {
        ulonglong2 w0[4], w1[4], w2[4];
#pragma unroll
        for (int jj = 0; jj < 4; jj++) {
            int j = tx + jj * 24;
            w0[jj] = *reinterpret_cast<const ulonglong2*>(&Ws[0 * WS_MAT + j * WS_STRIDE + k]);
            w1[jj] = *reinterpret_cast<const ulonglong2*>(&Ws[1 * WS_MAT + j * WS_STRIDE + k]);
            w2[jj] = *reinterpret_cast<const ulonglong2*>(&Ws[2 * WS_MAT + j * WS_STRIDE + k]);
        }
#pragma unroll
        for (int r = 0; r < 4; r++) {
            ulonglong2 xv = *reinterpret_cast<const ulonglong2*>(&xrow[r * DD + k]);
            ulonglong2 av = *reinterpret_cast<const ulonglong2*>(&t1row[r * DD + k]);
            ulonglong2 bv = *reinterpret_cast<const ulonglong2*>(&t2row[r * DD + k]);
#pragma unroll
            for (int jj = 0; jj < 4; jj++) {
                ffma2(acc[r][jj], xv.x, w0[jj].x);
                ffma2(acc[r][jj], xv.y, w0[jj].y);
                ffma2(acc[r][jj], av.x, w1[jj].x);
                ffma2(acc[r][jj], av.y, w1[jj].y);
                ffma2(acc[r][jj], bv.x, w2[jj].x);
                ffma2(acc[r][jj], bv.y, w2[jj].y);
            }
        }
    }

    // epilogue: combine halves, add bias, write pre-BN output + column stats
#pragma unroll
    for (int jj = 0; jj < 4; jj++) {
        int j = tx + jj * 24;
        float bj = bs[j];
        float s = 0.f, s2 = 0.f;
#pragma unroll
        for (int r = 0; r < 4; r++) {
            int row = base + ty * 4 + r;
            if (row < NN) {
                unsigned int lo_b, hi_b;
                asm("mov.b64 {%0, %1}, %2;" : "=r"(lo_b), "=r"(hi_b) : "l"(acc[r][jj]));
                float v = __uint_as_float(lo_b) + __uint_as_float(hi_b) + bj;
                g_acc[row * DD + j] = v;
                s += v; s2 += v * v;
            }
        }
        atomicAdd(&g_colsum[j], s);
        atomicAdd(&g_colsumsq[j], s2);
    }
}

// ---------------- BatchNorm: stats finalize fused into apply ----------------
__global__ void bn_apply_kernel(const float* __restrict__ gamma,
                                const float* __restrict__ beta,
                                float* __restrict__ out) {
    __shared__ float sc[DD], sh[DD];
    if (threadIdx.x < DD) {
        int j = threadIdx.x;
        float inv_n = 1.0f / (float)NN;
        float mean = g_colsum[j] * inv_n;
        float var = fmaxf(g_colsumsq[j] * inv_n - mean * mean, 0.f);
        float istd = rsqrtf(var + 1e-5f);
        float s = gamma[j] * istd;
        sc[j] = s;
        sh[j] = beta[j] - mean * s;
    }
    __syncthreads();
    int tid = blockIdx.x * blockDim.x + threadIdx.x;
    int stride = gridDim.x * blockDim.x;
    const float4* in4 = reinterpret_cast<const float4*>(g_acc);
    float4* o4 = reinterpret_cast<float4*>(out);
    for (int i = tid; i < NV4; i += stride) {
        int c4 = i % (DD / 4);
        int j = c4 * 4;
        float4 v = in4[i];
        o4[i] = make_float4(v.x * sc[j]     + sh[j],
                            v.y * sc[j + 1] + sh[j + 1],
                            v.z * sc[j + 2] + sh[j + 2],
                            v.w * sc[j + 3] + sh[j + 3]);
    }
}

// ---------------- launch ----------------------------------------------------
extern "C" void kernel_launch(void* const* d_in, const int* in_sizes, int n_in,
                              void* d_out, int out_size) {
    const float* x     = (const float*)d_in[0];
    const int*   ei    = (const int*)d_in[1];
    const float* W     = (const float*)d_in[2];
    const float* bias  = (const float*)d_in[3];
    const float* gamma = (const float*)d_in[4];
    const float* beta  = (const float*)d_in[5];
    float* out = (float*)d_out;

    cudaFuncSetAttribute(gemm_kernel,
                         cudaFuncAttributeMaxDynamicSharedMemorySize, SMEM_BYTES);

    zero_kernel<<<2048, 256>>>();
    deg_kernel<<<(EE + 255) / 256, 256>>>(ei);
    edge_build_kernel<<<(EE + 255) / 256, 256>>>(ei);
    // prop 1: T1 = L_hat @ x
    spmm_kernel<<<EE / 32, 256>>>(0, x);
    // prop 2: P = L_hat @ T1  (T2 = 2P - x computed in GEMM)
    spmm_kernel<<<EE / 32, 256>>>(1, x);
    gemm_kernel<<<(NN + RPB - 1) / RPB, GEMM_THREADS, SMEM_BYTES>>>(x, W, bias);
    bn_apply_kernel<<<2048, 256>>>(gamma, beta, out);
}

// round 12
// speedup vs baseline: 1.4254x; 1.1683x over previous
#include <cuda_runtime.h>

#define NN 50000
#define EE 800000
#define DD 96
#define NV4 (NN * DD / 4)

// ---------------- scratch (device globals; no allocation allowed) ----------
__device__ __align__(256) float g_deg[NN];
__device__ __align__(256) uint2 g_edge[EE];      // {(r<<16)|c, norm bits}
__device__ __align__(256) float g_T1[NN * DD];
__device__ __align__(256) float g_P[NN * DD];
__device__ __align__(256) float g_acc[NN * DD];  // pre-BN output
__device__ __align__(256) float g_colsum[DD];
__device__ __align__(256) float g_colsumsq[DD];

// ---------------- packed f32x2 FMA (SASS FFMA2) -----------------------------
__device__ __forceinline__ void ffma2(unsigned long long& d,
                                      unsigned long long a,
                                      unsigned long long b) {
    asm("fma.rn.f32x2 %0, %1, %2, %0;" : "+l"(d) : "l"(a), "l"(b));
}

// ---------------- zero scratch ---------------------------------------------
__global__ void zero_kernel() {
    int tid = blockIdx.x * blockDim.x + threadIdx.x;
    int stride = gridDim.x * blockDim.x;
    float4* t1 = reinterpret_cast<float4*>(g_T1);
    float4* p  = reinterpret_cast<float4*>(g_P);
    float4 z = make_float4(0.f, 0.f, 0.f, 0.f);
    for (int i = tid; i < NV4; i += stride) { t1[i] = z; p[i] = z; }
    for (int i = tid; i < NN; i += stride) g_deg[i] = 0.f;
    if (tid < DD) { g_colsum[tid] = 0.f; g_colsumsq[tid] = 0.f; }
}

// ---------------- degree histogram -----------------------------------------
__global__ void deg_kernel(const int* __restrict__ ei) {
    int e = blockIdx.x * blockDim.x + threadIdx.x;
    if (e >= EE) return;
    int r = ei[e], c = ei[EE + e];
    if (r != c) atomicAdd(&g_deg[r], 1.0f);
}

// ---------------- packed edge list with norm (dis inline) -------------------
__global__ void edge_build_kernel(const int* __restrict__ ei) {
    int e = blockIdx.x * blockDim.x + threadIdx.x;
    if (e >= EE) return;
    int r = ei[e], c = ei[EE + e];
    float nrm = 0.f;
    if (r != c) {
        float dr = g_deg[r], dc = g_deg[c];
        float ir = (dr > 0.f) ? rsqrtf(fmaxf(dr, 1e-12f)) : 0.f;
        float ic = (dc > 0.f) ? rsqrtf(fmaxf(dc, 1e-12f)) : 0.f;
        nrm = -ir * ic;
    }
    g_edge[e] = make_uint2(((unsigned)r << 16) | (unsigned)c,
                           (unsigned)__float_as_int(nrm));
}

// ---------------- SpMM (round-11 verbatim) ----------------------------------
__global__ void spmm_kernel(int pass, const float* __restrict__ x) {
    const float4* src = (pass == 0) ? reinterpret_cast<const float4*>(x)
                                    : reinterpret_cast<const float4*>(g_T1);
    float* dst = (pass == 0) ? g_T1 : g_P;

    int warp_id = (blockIdx.x * blockDim.x + threadIdx.x) >> 5;
    int lane = threadIdx.x & 31;
    int e = warp_id * 4 + (lane >> 3);
    if (e >= EE) return;

    uint2 ed = g_edge[e];
    float nrm = __int_as_float((int)ed.y);
    if (nrm == 0.f) return;
    int r = (int)(ed.x >> 16);
    int c = (int)(ed.x & 0xFFFFu);
    int chunk = lane & 7;

    const float4* srow = src + r * (DD / 4);
    float* drow = dst + c * DD;

#pragma unroll
    for (int s = 0; s < 3; s++) {
        int idx = chunk + 8 * s;
        float4 v = __ldg(srow + idx);
        float a = nrm * v.x, b = nrm * v.y, cc = nrm * v.z, d = nrm * v.w;
        float* addr = drow + idx * 4;
        asm volatile("red.global.add.v4.f32 [%0], {%1, %2, %3, %4};"
                     :: "l"(addr), "f"(a), "f"(b), "f"(cc), "f"(d)
                     : "memory");
    }
}

// ---------------- persistent GEMM + bias + column stats ---------------------
// out = x@W0 + T1@W1 + (2P - x)@W2 + bias.
// 148 persistent blocks; W staged once; next tile's rows register-prefetched
// under the FFMA2 stream; BN stats reduced per-block through smem.
#define GEMM_THREADS 384
#define RPB 64
#define NSM 148
#define WS_STRIDE 100
#define WS_MAT (DD * WS_STRIDE)
#define GBLK ((NN + RPB - 1) / RPB)              // 782
#define ROW4 (DD / 4)                            // 24 float4 per row
#define TILE4 (RPB * ROW4)                       // 1536 float4 per array
#define PFQ (TILE4 / GEMM_THREADS)               // 4 float4/thread/array
#define SMEM_FLOATS (3 * WS_MAT + DD + 3 * RPB * DD + 2 * DD)
#define SMEM_BYTES (SMEM_FLOATS * 4)

__global__ __launch_bounds__(GEMM_THREADS, 1)
void gemm_kernel(const float* __restrict__ x, const float* __restrict__ W,
                 const float* __restrict__ bias) {
    extern __shared__ float smem[];
    float* Ws   = smem;                    // [3][96*100]
    float* bs   = Ws + 3 * WS_MAT;         // [96]
    float* xs   = bs + DD;                 // [64*96]
    float* t1s  = xs + RPB * DD;
    float* t2s  = t1s + RPB * DD;
    float* stat = t2s + RPB * DD;          // [2][96]

    int tid = threadIdx.x;

    // stage W transposed (once): Ws[kk][j*100 + k] = W[kk][k][j]
    for (int i = tid; i < 3 * DD * DD; i += GEMM_THREADS) {
        int kk = i / (DD * DD);
        int rem = i - kk * DD * DD;
        int k = rem / DD;
        int j = rem - k * DD;
        Ws[kk * WS_MAT + j * WS_STRIDE + k] = W[i];
    }
    if (tid < DD) bs[tid] = bias[tid];
    if (tid < 2 * DD) stat[tid] = 0.f;

    const float4* x4  = reinterpret_cast<const float4*>(x);
    const float4* t14 = reinterpret_cast<const float4*>(g_T1);
    const float4* p4  = reinterpret_cast<const float4*>(g_P);
    float4* xs4  = reinterpret_cast<float4*>(xs);
    float4* t1s4 = reinterpret_cast<float4*>(t1s);
    float4* t2s4 = reinterpret_cast<float4*>(t2s);

    int tx = tid % 24;           // j in {tx, tx+24, tx+48, tx+72}
    int ty = tid / 24;           // rows [base + ty*4, +4)

    float4 pf[3 * PFQ];          // prefetch regs: {x, t1, t2} x 4 chunks

    // ---- prefetch helper (inlined via lambda-free macro-ish loop) ----
    int tile = blockIdx.x;
    {
#pragma unroll
        for (int q = 0; q < PFQ; q++) {
            int idx = tid + q * GEMM_THREADS;
            int row = tile * RPB + idx / ROW4;
            float4 xv = make_float4(0.f, 0.f, 0.f, 0.f), t1v = xv, t2v = xv;
            if (row < NN) {
                int gi = row * ROW4 + (idx % ROW4);
                xv = __ldg(x4 + gi);
                t1v = t14[gi];
                float4 pv = p4[gi];
                t2v = make_float4(2.f * pv.x - xv.x, 2.f * pv.y - xv.y,
                                  2.f * pv.z - xv.z, 2.f * pv.w - xv.w);
            }
            pf[q * 3 + 0] = xv; pf[q * 3 + 1] = t1v; pf[q * 3 + 2] = t2v;
        }
    }
    __syncthreads();             // W + stat staged
#pragma unroll
    for (int q = 0; q < PFQ; q++) {
        int idx = tid + q * GEMM_THREADS;
        xs4[idx] = pf[q * 3 + 0]; t1s4[idx] = pf[q * 3 + 1]; t2s4[idx] = pf[q * 3 + 2];
    }
    __syncthreads();

    float cs[4] = {0.f, 0.f, 0.f, 0.f};
    float cs2[4] = {0.f, 0.f, 0.f, 0.f};

    for (;;) {
        int next = tile + NSM;
        bool has_next = (next < GBLK);

        // issue next tile's loads early — latency hides under FFMA2 stream
        if (has_next) {
#pragma unroll
            for (int q = 0; q < PFQ; q++) {
                int idx = tid + q * GEMM_THREADS;
                int row = next * RPB + idx / ROW4;
                float4 xv = make_float4(0.f, 0.f, 0.f, 0.f), t1v = xv, t2v = xv;
                if (row < NN) {
                    int gi = row * ROW4 + (idx % ROW4);
                    xv = __ldg(x4 + gi);
                    t1v = t14[gi];
                    float4 pv = p4[gi];
                    t2v = make_float4(2.f * pv.x - xv.x, 2.f * pv.y - xv.y,
                                      2.f * pv.z - xv.z, 2.f * pv.w - xv.w);
                }
                pf[q * 3 + 0] = xv; pf[q * 3 + 1] = t1v; pf[q * 3 + 2] = t2v;
            }
        }

        // ---- compute current tile (FFMA2) ----
        unsigned long long acc[4][4];
#pragma unroll
        for (int r = 0; r < 4; r++)
#pragma unroll
            for (int jj = 0; jj < 4; jj++) acc[r][jj] = 0ULL;

        const float* xrow  = xs  + ty * 4 * DD;
        const float* t1row = t1s + ty * 4 * DD;
        const float* t2row = t2s + ty * 4 * DD;

        for (int k = 0; k < DD; k += 4) {
            ulonglong2 w0[4], w1[4], w2[4];
#pragma unroll
            for (int jj = 0; jj < 4; jj++) {
                int j = tx + jj * 24;
                w0[jj] = *reinterpret_cast<const ulonglong2*>(&Ws[0 * WS_MAT + j * WS_STRIDE + k]);
                w1[jj] = *reinterpret_cast<const ulonglong2*>(&Ws[1 * WS_MAT + j * WS_STRIDE + k]);
                w2[jj] = *reinterpret_cast<const ulonglong2*>(&Ws[2 * WS_MAT + j * WS_STRIDE + k]);
            }
#pragma unroll
            for (int r = 0; r < 4; r++) {
                ulonglong2 xv = *reinterpret_cast<const ulonglong2*>(&xrow[r * DD + k]);
                ulonglong2 av = *reinterpret_cast<const ulonglong2*>(&t1row[r * DD + k]);
                ulonglong2 bv = *reinterpret_cast<const ulonglong2*>(&t2row[r * DD + k]);
#pragma unroll
                for (int jj = 0; jj < 4; jj++) {
                    ffma2(acc[r][jj], xv.x, w0[jj].x);
                    ffma2(acc[r][jj], xv.y, w0[jj].y);
                    ffma2(acc[r][jj], av.x, w1[jj].x);
                    ffma2(acc[r][jj], av.y, w1[jj].y);
                    ffma2(acc[r][jj], bv.x, w2[jj].x);
                    ffma2(acc[r][jj], bv.y, w2[jj].y);
                }
            }
        }

        // ---- epilogue: write pre-BN output, accumulate stats in regs ----
        int base = tile * RPB;
#pragma unroll
        for (int jj = 0; jj < 4; jj++) {
            int j = tx + jj * 24;
            float bj = bs[j];
#pragma unroll
            for (int r = 0; r < 4; r++) {
                int row = base + ty * 4 + r;
                if (row < NN) {
                    unsigned int lo_b, hi_b;
                    asm("mov.b64 {%0, %1}, %2;" : "=r"(lo_b), "=r"(hi_b) : "l"(acc[r][jj]));
                    float v = __uint_as_float(lo_b) + __uint_as_float(hi_b) + bj;
                    g_acc[row * DD + j] = v;
                    cs[jj] += v; cs2[jj] += v * v;
                }
            }
        }

        if (!has_next) break;
        __syncthreads();         // everyone done reading smem tiles
#pragma unroll
        for (int q = 0; q < PFQ; q++) {
            int idx = tid + q * GEMM_THREADS;
            xs4[idx] = pf[q * 3 + 0]; t1s4[idx] = pf[q * 3 + 1]; t2s4[idx] = pf[q * 3 + 2];
        }
        __syncthreads();
        tile = next;
    }

    // ---- per-block stats reduction -> 2 global atomics per column ----
    __syncthreads();
#pragma unroll
    for (int jj = 0; jj < 4; jj++) {
        int j = tx + jj * 24;
        atomicAdd(&stat[j], cs[jj]);
        atomicAdd(&stat[DD + j], cs2[jj]);
    }
    __syncthreads();
    if (tid < DD) {
        atomicAdd(&g_colsum[tid], stat[tid]);
        atomicAdd(&g_colsumsq[tid], stat[DD + tid]);
    }
}

// ---------------- BatchNorm: stats finalize fused into apply ----------------
__global__ void bn_apply_kernel(const float* __restrict__ gamma,
                                const float* __restrict__ beta,
                                float* __restrict__ out) {
    __shared__ float sc[DD], sh[DD];
    if (threadIdx.x < DD) {
        int j = threadIdx.x;
        float inv_n = 1.0f / (float)NN;
        float mean = g_colsum[j] * inv_n;
        float var = fmaxf(g_colsumsq[j] * inv_n - mean * mean, 0.f);
        float istd = rsqrtf(var + 1e-5f);
        float s = gamma[j] * istd;
        sc[j] = s;
        sh[j] = beta[j] - mean * s;
    }
    __syncthreads();
    int tid = blockIdx.x * blockDim.x + threadIdx.x;
    int stride = gridDim.x * blockDim.x;
    const float4* in4 = reinterpret_cast<const float4*>(g_acc);
    float4* o4 = reinterpret_cast<float4*>(out);
    for (int i = tid; i < NV4; i += stride) {
        int c4 = i % (DD / 4);
        int j = c4 * 4;
        float4 v = in4[i];
        o4[i] = make_float4(v.x * sc[j]     + sh[j],
                            v.y * sc[j + 1] + sh[j + 1],
                            v.z * sc[j + 2] + sh[j + 2],
                            v.w * sc[j + 3] + sh[j + 3]);
    }
}

// ---------------- launch ----------------------------------------------------
extern "C" void kernel_launch(void* const* d_in, const int* in_sizes, int n_in,
                              void* d_out, int out_size) {
    const float* x     = (const float*)d_in[0];
    const int*   ei    = (const int*)d_in[1];
    const float* W     = (const float*)d_in[2];
    const float* bias  = (const float*)d_in[3];
    const float* gamma = (const float*)d_in[4];
    const float* beta  = (const float*)d_in[5];
    float* out = (float*)d_out;

    cudaFuncSetAttribute(gemm_kernel,
                         cudaFuncAttributeMaxDynamicSharedMemorySize, SMEM_BYTES);

    zero_kernel<<<2048, 256>>>();
    deg_kernel<<<(EE + 255) / 256, 256>>>(ei);
    edge_build_kernel<<<(EE + 255) / 256, 256>>>(ei);
    // prop 1: T1 = L_hat @ x
    spmm_kernel<<<EE / 32, 256>>>(0, x);
    // prop 2: P = L_hat @ T1  (T2 = 2P - x staged in GEMM)
    spmm_kernel<<<EE / 32, 256>>>(1, x);
    gemm_kernel<<<NSM, GEMM_THREADS, SMEM_BYTES>>>(x, W, bias);
    bn_apply_kernel<<<2048, 256>>>(gamma, beta, out);
}

// round 13
// speedup vs baseline: 1.7852x; 1.2524x over previous
#include <cuda_runtime.h>

#define NN 50000
#define EE 800000
#define DD 96
#define NV4 (NN * DD / 4)
#define NBLK ((NN + 255) / 256)        // 196 scan blocks

// ---------------- scratch (device globals; no allocation allowed) ----------
__device__ __align__(256) float g_deg[NN];      // out-degree (by row)
__device__ __align__(256) int   g_cnt[NN];      // in-degree (by col)
__device__ __align__(256) int   g_ptr[NN + 1];  // CSR row pointers (by dst)
__device__ __align__(256) int   g_fill[NN];     // atomic cursors
__device__ __align__(256) int   g_bsum[256];    // scan block sums
__device__ __align__(256) int   g_boff[256];    // scan block offsets
__device__ __align__(256) int2  g_cedge[EE];    // {src_row, norm bits}
__device__ __align__(256) float g_T1[NN * DD];
__device__ __align__(256) float g_P[NN * DD];
__device__ __align__(256) float g_acc[NN * DD];
__device__ __align__(256) float g_colsum[DD];
__device__ __align__(256) float g_colsumsq[DD];

// ---------------- packed f32x2 FMA (SASS FFMA2) -----------------------------
__device__ __forceinline__ void ffma2(unsigned long long& d,
                                      unsigned long long a,
                                      unsigned long long b) {
    asm("fma.rn.f32x2 %0, %1, %2, %0;" : "+l"(d) : "l"(a), "l"(b));
}

// ---------------- zero small scratch ----------------------------------------
__global__ void zero_kernel() {
    int tid = blockIdx.x * blockDim.x + threadIdx.x;
    int stride = gridDim.x * blockDim.x;
    for (int i = tid; i < NN; i += stride) { g_deg[i] = 0.f; g_cnt[i] = 0; }
    if (tid < DD) { g_colsum[tid] = 0.f; g_colsumsq[tid] = 0.f; }
}

// ---------------- histogram: out-degree (row) + in-degree (col) -------------
__global__ void hist_kernel(const int* __restrict__ ei) {
    int e = blockIdx.x * blockDim.x + threadIdx.x;
    if (e >= EE) return;
    int r = ei[e], c = ei[EE + e];
    if (r != c) {
        atomicAdd(&g_deg[r], 1.0f);
        atomicAdd(&g_cnt[c], 1);
    }
}

// ---------------- multi-block exclusive scan of g_cnt -> g_ptr --------------
__global__ void scan1_kernel() {                 // per-block scan + block sums
    __shared__ int sh[256];
    int i = blockIdx.x * 256 + threadIdx.x;
    int v = (i < NN) ? g_cnt[i] : 0;
    sh[threadIdx.x] = v;
    __syncthreads();
#pragma unroll
    for (int off = 1; off < 256; off <<= 1) {
        int t = (threadIdx.x >= off) ? sh[threadIdx.x - off] : 0;
        __syncthreads();
        sh[threadIdx.x] += t;
        __syncthreads();
    }
    if (i < NN) g_ptr[i] = sh[threadIdx.x] - v;  // block-local exclusive
    if (threadIdx.x == 255) g_bsum[blockIdx.x] = sh[255];
}

__global__ void scan2_kernel() {                 // scan the 196 block sums
    __shared__ int sh[256];
    int b = threadIdx.x;
    int v = (b < NBLK) ? g_bsum[b] : 0;
    sh[b] = v;
    __syncthreads();
#pragma unroll
    for (int off = 1; off < 256; off <<= 1) {
        int t = (b >= off) ? sh[b - off] : 0;
        __syncthreads();
        sh[b] += t;
        __syncthreads();
    }
    if (b < NBLK) g_boff[b] = sh[b] - v;
    if (b == 255) g_ptr[NN] = sh[255];           // total kept edges
}

__global__ void scan3_kernel() {                 // add offsets, init cursors
    int i = blockIdx.x * 256 + threadIdx.x;
    if (i >= NN) return;
    int p = g_ptr[i] + g_boff[blockIdx.x];
    g_ptr[i] = p;
    g_fill[i] = p;
}

// ---------------- scatter edges into CSR buckets (norm inline) --------------
__global__ void scatter_kernel(const int* __restrict__ ei) {
    int e = blockIdx.x * blockDim.x + threadIdx.x;
    if (e >= EE) return;
    int r = ei[e], c = ei[EE + e];
    if (r == c) return;
    float dr = g_deg[r], dc = g_deg[c];
    float ir = (dr > 0.f) ? rsqrtf(fmaxf(dr, 1e-12f)) : 0.f;
    float ic = (dc > 0.f) ? rsqrtf(fmaxf(dc, 1e-12f)) : 0.f;
    float nrm = -ir * ic;
    int pos = atomicAdd(&g_fill[c], 1);
    g_cedge[pos] = make_int2(r, __float_as_int(nrm));
}

// ---------------- pull-mode SpMM: dst[n] = sum_e norm[e]*src[row[e]] --------
// One warp per destination node; lane covers features {lane, +32, +64}.
// Plain coalesced stores; no atomics; no zero-init needed.
__global__ void spmm_pull_kernel(int pass, const float* __restrict__ x) {
    const float* src = (pass == 0) ? x : g_T1;
    float* dst = (pass == 0) ? g_T1 : g_P;

    int node = (blockIdx.x * blockDim.x + threadIdx.x) >> 5;
    if (node >= NN) return;
    int lane = threadIdx.x & 31;

    int beg = g_ptr[node], end = g_ptr[node + 1];
    float a0 = 0.f, a1 = 0.f, a2 = 0.f;

    int e = beg;
    for (; e + 1 < end; e += 2) {
        int2 e0 = __ldg(&g_cedge[e]);
        int2 e1 = __ldg(&g_cedge[e + 1]);
        float n0 = __int_as_float(e0.y);
        float n1 = __int_as_float(e1.y);
        const float* s0 = src + e0.x * DD;
        const float* s1 = src + e1.x * DD;
        float v00 = __ldg(s0 + lane), v01 = __ldg(s0 + lane + 32), v02 = __ldg(s0 + lane + 64);
        float v10 = __ldg(s1 + lane), v11 = __ldg(s1 + lane + 32), v12 = __ldg(s1 + lane + 64);
        a0 += n0 * v00 + n1 * v10;
        a1 += n0 * v01 + n1 * v11;
        a2 += n0 * v02 + n1 * v12;
    }
    if (e < end) {
        int2 e0 = __ldg(&g_cedge[e]);
        float n0 = __int_as_float(e0.y);
        const float* s0 = src + e0.x * DD;
        a0 += n0 * __ldg(s0 + lane);
        a1 += n0 * __ldg(s0 + lane + 32);
        a2 += n0 * __ldg(s0 + lane + 64);
    }

    float* d = dst + node * DD;
    d[lane] = a0;
    d[lane + 32] = a1;
    d[lane + 64] = a2;
}

// ---------------- persistent GEMM + bias + column stats (round-12 verbatim) -
#define GEMM_THREADS 384
#define RPB 64
#define NSM 148
#define WS_STRIDE 100
#define WS_MAT (DD * WS_STRIDE)
#define GBLK ((NN + RPB - 1) / RPB)
#define ROW4 (DD / 4)
#define TILE4 (RPB * ROW4)
#define PFQ (TILE4 / GEMM_THREADS)
#define SMEM_FLOATS (3 * WS_MAT + DD + 3 * RPB * DD + 2 * DD)
#define SMEM_BYTES (SMEM_FLOATS * 4)

__global__ __launch_bounds__(GEMM_THREADS, 1)
void gemm_kernel(const float* __restrict__ x, const float* __restrict__ W,
                 const float* __restrict__ bias) {
    extern __shared__ float smem[];
    float* Ws   = smem;
    float* bs   = Ws + 3 * WS_MAT;
    float* xs   = bs + DD;
    float* t1s  = xs + RPB * DD;
    float* t2s  = t1s + RPB * DD;
    float* stat = t2s + RPB * DD;

    int tid = threadIdx.x;

    for (int i = tid; i < 3 * DD * DD; i += GEMM_THREADS) {
        int kk = i / (DD * DD);
        int rem = i - kk * DD * DD;
        int k = rem / DD;
        int j = rem - k * DD;
        Ws[kk * WS_MAT + j * WS_STRIDE + k] = W[i];
    }
    if (tid < DD) bs[tid] = bias[tid];
    if (tid < 2 * DD) stat[tid] = 0.f;

    const float4* x4  = reinterpret_cast<const float4*>(x);
    const float4* t14 = reinterpret_cast<const float4*>(g_T1);
    const float4* p4  = reinterpret_cast<const float4*>(g_P);
    float4* xs4  = reinterpret_cast<float4*>(xs);
    float4* t1s4 = reinterpret_cast<float4*>(t1s);
    float4* t2s4 = reinterpret_cast<float4*>(t2s);

    int tx = tid % 24;
    int ty = tid / 24;

    float4 pf[3 * PFQ];
    int tile = blockIdx.x;
    {
#pragma unroll
        for (int q = 0; q < PFQ; q++) {
            int idx = tid + q * GEMM_THREADS;
            int row = tile * RPB + idx / ROW4;
            float4 xv = make_float4(0.f, 0.f, 0.f, 0.f), t1v = xv, t2v = xv;
            if (row < NN) {
                int gi = row * ROW4 + (idx % ROW4);
                xv = __ldg(x4 + gi);
                t1v = t14[gi];
                float4 pv = p4[gi];
                t2v = make_float4(2.f * pv.x - xv.x, 2.f * pv.y - xv.y,
                                  2.f * pv.z - xv.z, 2.f * pv.w - xv.w);
            }
            pf[q * 3 + 0] = xv; pf[q * 3 + 1] = t1v; pf[q * 3 + 2] = t2v;
        }
    }
    __syncthreads();
#pragma unroll
    for (int q = 0; q < PFQ; q++) {
        int idx = tid + q * GEMM_THREADS;
        xs4[idx] = pf[q * 3 + 0]; t1s4[idx] = pf[q * 3 + 1]; t2s4[idx] = pf[q * 3 + 2];
    }
    __syncthreads();

    float cs[4] = {0.f, 0.f, 0.f, 0.f};
    float cs2[4] = {0.f, 0.f, 0.f, 0.f};

    for (;;) {
        int next = tile + NSM;
        bool has_next = (next < GBLK);

        if (has_next) {
#pragma unroll
            for (int q = 0; q < PFQ; q++) {
                int idx = tid + q * GEMM_THREADS;
                int row = next * RPB + idx / ROW4;
                float4 xv = make_float4(0.f, 0.f, 0.f, 0.f), t1v = xv, t2v = xv;
                if (row < NN) {
                    int gi = row * ROW4 + (idx % ROW4);
                    xv = __ldg(x4 + gi);
                    t1v = t14[gi];
                    float4 pv = p4[gi];
                    t2v = make_float4(2.f * pv.x - xv.x, 2.f * pv.y - xv.y,
                                      2.f * pv.z - xv.z, 2.f * pv.w - xv.w);
                }
                pf[q * 3 + 0] = xv; pf[q * 3 + 1] = t1v; pf[q * 3 + 2] = t2v;
            }
        }

        unsigned long long acc[4][4];
#pragma unroll
        for (int r = 0; r < 4; r++)
#pragma unroll
            for (int jj = 0; jj < 4; jj++) acc[r][jj] = 0ULL;

        const float* xrow  = xs  + ty * 4 * DD;
        const float* t1row = t1s + ty * 4 * DD;
        const float* t2row = t2s + ty * 4 * DD;

        for (int k = 0; k < DD; k += 4) {
            ulonglong2 w0[4], w1[4], w2[4];
#pragma unroll
            for (int jj = 0; jj < 4; jj++) {
                int j = tx + jj * 24;
                w0[jj] = *reinterpret_cast<const ulonglong2*>(&Ws[0 * WS_MAT + j * WS_STRIDE + k]);
                w1[jj] = *reinterpret_cast<const ulonglong2*>(&Ws[1 * WS_MAT + j * WS_STRIDE + k]);
                w2[jj] = *reinterpret_cast<const ulonglong2*>(&Ws[2 * WS_MAT + j * WS_STRIDE + k]);
            }
#pragma unroll
            for (int r = 0; r < 4; r++) {
                ulonglong2 xv = *reinterpret_cast<const ulonglong2*>(&xrow[r * DD + k]);
                ulonglong2 av = *reinterpret_cast<const ulonglong2*>(&t1row[r * DD + k]);
                ulonglong2 bv = *reinterpret_cast<const ulonglong2*>(&t2row[r * DD + k]);
#pragma unroll
                for (int jj = 0; jj < 4; jj++) {
                    ffma2(acc[r][jj], xv.x, w0[jj].x);
                    ffma2(acc[r][jj], xv.y, w0[jj].y);
                    ffma2(acc[r][jj], av.x, w1[jj].x);
                    ffma2(acc[r][jj], av.y, w1[jj].y);
                    ffma2(acc[r][jj], bv.x, w2[jj].x);
                    ffma2(acc[r][jj], bv.y, w2[jj].y);
                }
            }
        }

        int base = tile * RPB;
#pragma unroll
        for (int jj = 0; jj < 4; jj++) {
            int j = tx + jj * 24;
            float bj = bs[j];
#pragma unroll
            for (int r = 0; r < 4; r++) {
                int row = base + ty * 4 + r;
                if (row < NN) {
                    unsigned int lo_b, hi_b;
                    asm("mov.b64 {%0, %1}, %2;" : "=r"(lo_b), "=r"(hi_b) : "l"(acc[r][jj]));
                    float v = __uint_as_float(lo_b) + __uint_as_float(hi_b) + bj;
                    g_acc[row * DD + j] = v;
                    cs[jj] += v; cs2[jj] += v * v;
                }
            }
        }

        if (!has_next) break;
        __syncthreads();
#pragma unroll
        for (int q = 0; q < PFQ; q++) {
            int idx = tid + q * GEMM_THREADS;
            xs4[idx] = pf[q * 3 + 0]; t1s4[idx] = pf[q * 3 + 1]; t2s4[idx] = pf[q * 3 + 2];
        }
        __syncthreads();
        tile = next;
    }

    __syncthreads();
#pragma unroll
    for (int jj = 0; jj < 4; jj++) {
        int j = tx + jj * 24;
        atomicAdd(&stat[j], cs[jj]);
        atomicAdd(&stat[DD + j], cs2[jj]);
    }
    __syncthreads();
    if (tid < DD) {
        atomicAdd(&g_colsum[tid], stat[tid]);
        atomicAdd(&g_colsumsq[tid], stat[DD + tid]);
    }
}

// ---------------- BatchNorm: stats finalize fused into apply ----------------
__global__ void bn_apply_kernel(const float* __restrict__ gamma,
                                const float* __restrict__ beta,
                                float* __restrict__ out) {
    __shared__ float sc[DD], sh[DD];
    if (threadIdx.x < DD) {
        int j = threadIdx.x;
        float inv_n = 1.0f / (float)NN;
        float mean = g_colsum[j] * inv_n;
        float var = fmaxf(g_colsumsq[j] * inv_n - mean * mean, 0.f);
        float istd = rsqrtf(var + 1e-5f);
        float s = gamma[j] * istd;
        sc[j] = s;
        sh[j] = beta[j] - mean * s;
    }
    __syncthreads();
    int tid = blockIdx.x * blockDim.x + threadIdx.x;
    int stride = gridDim.x * blockDim.x;
    const float4* in4 = reinterpret_cast<const float4*>(g_acc);
    float4* o4 = reinterpret_cast<float4*>(out);
    for (int i = tid; i < NV4; i += stride) {
        int c4 = i % (DD / 4);
        int j = c4 * 4;
        float4 v = in4[i];
        o4[i] = make_float4(v.x * sc[j]     + sh[j],
                            v.y * sc[j + 1] + sh[j + 1],
                            v.z * sc[j + 2] + sh[j + 2],
                            v.w * sc[j + 3] + sh[j + 3]);
    }
}

// ---------------- launch ----------------------------------------------------
extern "C" void kernel_launch(void* const* d_in, const int* in_sizes, int n_in,
                              void* d_out, int out_size) {
    const float* x     = (const float*)d_in[0];
    const int*   ei    = (const int*)d_in[1];
    const float* W     = (const float*)d_in[2];
    const float* bias  = (const float*)d_in[3];
    const float* gamma = (const float*)d_in[4];
    const float* beta  = (const float*)d_in[5];
    float* out = (float*)d_out;

    cudaFuncSetAttribute(gemm_kernel,
                         cudaFuncAttributeMaxDynamicSharedMemorySize, SMEM_BYTES);

    zero_kernel<<<256, 256>>>();
    hist_kernel<<<(EE + 255) / 256, 256>>>(ei);
    scan1_kernel<<<NBLK, 256>>>();
    scan2_kernel<<<1, 256>>>();
    scan3_kernel<<<NBLK, 256>>>();
    scatter_kernel<<<(EE + 255) / 256, 256>>>(ei);
    // prop 1: T1 = L_hat @ x  (pull, no atomics, no zero-init)
    spmm_pull_kernel<<<(NN * 32 + 255) / 256, 256>>>(0, x);
    // prop 2: P = L_hat @ T1
    spmm_pull_kernel<<<(NN * 32 + 255) / 256, 256>>>(1, x);
    gemm_kernel<<<NSM, GEMM_THREADS, SMEM_BYTES>>>(x, W, bias);
    bn_apply_kernel<<<2048, 256>>>(gamma, beta, out);
}